// round 12
// baseline (speedup 1.0000x reference)
#include <cuda_runtime.h>

#define NB 4096
#define NEG 0.02f
// (1/sqrt(5)) * log2(e)
#define CEXP 0.6451928329f

typedef unsigned long long u64;

// hop-2 output: [B*N1, 30]
__device__ float g_h1[NB * 16 * 30];

// ---------------------------------------------------------------------------
__device__ __forceinline__ u64 pk2(float lo, float hi) {
    u64 v; asm("mov.b64 %0,{%1,%2};" : "=l"(v) : "f"(lo), "f"(hi)); return v;
}
__device__ __forceinline__ float2 upk2(u64 v) {
    float2 r; asm("mov.b64 {%0,%1},%2;" : "=f"(r.x), "=f"(r.y) : "l"(v)); return r;
}
__device__ __forceinline__ u64 f2fma(u64 a, u64 b, u64 c) {
    u64 d; asm("fma.rn.f32x2 %0,%1,%2,%3;" : "=l"(d) : "l"(a), "l"(b), "l"(c));
    return d;
}
__device__ __forceinline__ u64 f2add(u64 a, u64 b) {
    u64 d; asm("add.rn.f32x2 %0,%1,%2;" : "=l"(d) : "l"(a), "l"(b));
    return d;
}
__device__ __forceinline__ float ex2f(float x) {
    float r; asm("ex2.approx.f32 %0,%1;" : "=f"(r) : "f"(x)); return r;
}
__device__ __forceinline__ float rcpf(float x) {
    float r; asm("rcp.approx.f32 %0,%1;" : "=f"(r) : "f"(x)); return r;
}

// packed dot, 4 accumulators: 32-float weight row (pad zeroed) vs 16 u64
__device__ __forceinline__ float dotp(const float* __restrict__ wrow,
                                      const u64 (&v)[16]) {
    const ulonglong2* w2 = (const ulonglong2*)wrow;
    u64 a0 = 0ull, a1 = 0ull, a2 = 0ull, a3 = 0ull;
#pragma unroll
    for (int kk = 0; kk < 2; kk++) {
        ulonglong2 wa = w2[4 * kk + 0];
        ulonglong2 wb = w2[4 * kk + 1];
        ulonglong2 wc = w2[4 * kk + 2];
        ulonglong2 wd = w2[4 * kk + 3];
        a0 = f2fma(wa.x, v[8 * kk + 0], a0);
        a1 = f2fma(wa.y, v[8 * kk + 1], a1);
        a2 = f2fma(wb.x, v[8 * kk + 2], a2);
        a3 = f2fma(wb.y, v[8 * kk + 3], a3);
        a0 = f2fma(wc.x, v[8 * kk + 4], a0);
        a1 = f2fma(wc.y, v[8 * kk + 5], a1);
        a2 = f2fma(wd.x, v[8 * kk + 6], a2);
        a3 = f2fma(wd.y, v[8 * kk + 7], a3);
    }
    u64 s = f2add(f2add(a0, a1), f2add(a2, a3));
    float2 f = upk2(s);
    return f.x + f.y;
}

// stage1 for one sequence row: y = leaky(x @ lw^T + lb), packed result
__device__ __forceinline__ void stage1_one(const float* __restrict__ xrow,
                                           const float* __restrict__ lw_s,
                                           const float* __restrict__ lb_s,
                                           u64 (&yp)[16]) {
    u64 xp[16];
#pragma unroll
    for (int k = 0; k < 15; k++) {
        float2 t = *(const float2*)(xrow + 2 * k);
        xp[k] = pk2(t.x, t.y);
    }
    xp[15] = 0ull;
#pragma unroll
    for (int jj = 0; jj < 15; jj++) {
        float y0 = lb_s[2 * jj]     + dotp(lw_s + (2 * jj) * 32, xp);
        float y1 = lb_s[2 * jj + 1] + dotp(lw_s + (2 * jj + 1) * 32, xp);
        y0 = fmaxf(y0, NEG * y0);
        y1 = fmaxf(y1, NEG * y1);
        yp[jj] = pk2(y0, y1);
    }
    yp[15] = 0ull;
}

// ---------------------------------------------------------------------------
// sm layout: lw 0..959 | iw 960..3839 | owT 3840..4799 (TRANSPOSED) |
//            lb 4800 | ib 4832 | ob 4928..4959
//            (q-rows of iw and q-bias pre-scaled by CEXP)
// ---------------------------------------------------------------------------
__device__ __forceinline__ void stage_weights(float* sm, int tid, int nthr,
                                              const float* lw, const float* lb,
                                              const float* iw, const float* ib,
                                              const float* ow, const float* ob) {
    for (int i = tid; i < 4800; i += nthr) {
        int row = i >> 5, col = i & 31;
        float v = 0.f;
        if (col < 30) {
            if (row < 30)       v = lw[row * 30 + col];
            else if (row < 120) {
                v = iw[(row - 30) * 30 + col];
                if (row < 60) v *= CEXP;            // fold attn scale into q
            } else                v = ow[col * 30 + (row - 120)];  // owT
        }
        sm[i] = v;
    }
    if (tid < 30) sm[4800 + tid] = lb[tid];
    if (tid < 90) sm[4832 + tid] = (tid < 30) ? ib[tid] * CEXP : ib[tid];
    if (tid < 32) sm[4928 + tid] = (tid < 30) ? ob[tid] : 0.f;
}

// ===========================================================================
// hop2: 2 warps per sequence (heads split 3+3), 4 sequences per 256-thr CTA.
// Per-seq buffer (floats), 2976:
//   warp-half w in {0,1}: base = w*960
//     KA  : ulonglong2[96] [base+0,   base+384)
//     KV4 : u64[96]        [base+384, base+576)
//     VA  : ulonglong2[96] [base+576, base+960)
//   OS : float[32][33]     [1920, 2976)
// ===========================================================================
#define BUFF2 2976
#define SPC 4
#define NSEQ2 (NB * 16)
#define SMEM1_FLOATS (4960 + SPC * BUFF2)   // 16864 -> 67,456 B

__global__ void __launch_bounds__(256, 3) hop2_kernel(
    const float* __restrict__ x2,
    const float* __restrict__ lw, const float* __restrict__ lb,
    const float* __restrict__ iw, const float* __restrict__ ib,
    const float* __restrict__ ow, const float* __restrict__ ob) {
    extern __shared__ float sm[];
    const int tid = threadIdx.x;
    stage_weights(sm, tid, 256, lw, lb, iw, ib, ow, ob);
    __syncthreads();

    const float* iw_s  = sm + 960;
    const float* owT_s = sm + 3840;
    const float* ib_s  = sm + 4832;
    const float* ob_s  = sm + 4928;

    const int w = tid >> 5, r = tid & 31;
    const int seq = w >> 1, half = w & 1;
    const long sg = (long)blockIdx.x * SPC + seq;
    float* buf   = sm + 4960 + seq * BUFF2;
    float* mybuf = buf + half * 960;
    float* OS    = buf + 1920;              // [32][33]

    ulonglong2* KA  = (ulonglong2*)mybuf;
    u64*        KV4 = (u64*)(mybuf + 384);
    ulonglong2* VA  = (ulonglong2*)(mybuf + 576);

    // ---- stage 1 (duplicated across the pair; FMA is cheap) ---------------
    u64 yp[16];
    stage1_one(x2 + (sg * 32 + r) * 30, sm, sm + 4800, yp);

    // ---- qkv for this warp's 3 heads --------------------------------------
    const int hb = 3 * half;
    u64 q01[3], q23[3];
    float q4[3];
#pragma unroll
    for (int j = 0; j < 3; j++) {
        const int h = hb + j;
        float a0 = ib_s[h * 5 + 0] + dotp(iw_s + (h * 5 + 0) * 32, yp);
        float a1 = ib_s[h * 5 + 1] + dotp(iw_s + (h * 5 + 1) * 32, yp);
        float a2 = ib_s[h * 5 + 2] + dotp(iw_s + (h * 5 + 2) * 32, yp);
        float a3 = ib_s[h * 5 + 3] + dotp(iw_s + (h * 5 + 3) * 32, yp);
        float a4 = ib_s[h * 5 + 4] + dotp(iw_s + (h * 5 + 4) * 32, yp);
        q01[j] = pk2(a0, a1); q23[j] = pk2(a2, a3); q4[j] = a4;

        float k0 = ib_s[30 + h * 5 + 0] + dotp(iw_s + (30 + h * 5 + 0) * 32, yp);
        float k1 = ib_s[30 + h * 5 + 1] + dotp(iw_s + (30 + h * 5 + 1) * 32, yp);
        float k2 = ib_s[30 + h * 5 + 2] + dotp(iw_s + (30 + h * 5 + 2) * 32, yp);
        float k3 = ib_s[30 + h * 5 + 3] + dotp(iw_s + (30 + h * 5 + 3) * 32, yp);
        float k4 = ib_s[30 + h * 5 + 4] + dotp(iw_s + (30 + h * 5 + 4) * 32, yp);
        float v0 = ib_s[60 + h * 5 + 0] + dotp(iw_s + (60 + h * 5 + 0) * 32, yp);
        float v1 = ib_s[60 + h * 5 + 1] + dotp(iw_s + (60 + h * 5 + 1) * 32, yp);
        float v2 = ib_s[60 + h * 5 + 2] + dotp(iw_s + (60 + h * 5 + 2) * 32, yp);
        float v3 = ib_s[60 + h * 5 + 3] + dotp(iw_s + (60 + h * 5 + 3) * 32, yp);
        float v4 = ib_s[60 + h * 5 + 4] + dotp(iw_s + (60 + h * 5 + 4) * 32, yp);

        ulonglong2 kk; kk.x = pk2(k0, k1); kk.y = pk2(k2, k3);
        KA[j * 32 + r]  = kk;
        KV4[j * 32 + r] = pk2(k4, v4);
        ulonglong2 vv; vv.x = pk2(v0, v1); vv.y = pk2(v2, v3);
        VA[j * 32 + r]  = vv;
    }
    __syncwarp();          // staging is warp-local (this warp's heads only)

    // ---- attention for this warp's 3 heads --------------------------------
#pragma unroll
    for (int j = 0; j < 3; j++) {
        const int h = hb + j;
        u64 a01 = 0ull, a23 = 0ull;
        float a4 = 0.f, es = 0.f;
#pragma unroll 8
        for (int t = 0; t < 32; t++) {
            ulonglong2 ka = KA[j * 32 + t];
            float2 kv4 = upk2(KV4[j * 32 + t]);
            u64 s2 = f2fma(ka.x, q01[j], f2fma(ka.y, q23[j], 0ull));
            float2 sp = upk2(s2);
            float e = ex2f(fmaf(q4[j], kv4.x, sp.x + sp.y));
            u64 ee = pk2(e, e);
            ulonglong2 va = VA[j * 32 + t];
            a01 = f2fma(ee, va.x, a01);
            a23 = f2fma(ee, va.y, a23);
            a4  = fmaf(e, kv4.y, a4);
            es += e;
        }
        float inv = rcpf(es);
        float2 p01 = upk2(a01), p23 = upk2(a23);
        float* os = OS + r * 33 + h * 5;
        os[0] = p01.x * inv;
        os[1] = p01.y * inv;
        os[2] = p23.x * inv;
        os[3] = p23.y * inv;
        os[4] = a4 * inv;
    }

    // ---- pair barrier: both warps' OS halves must be complete -------------
    asm volatile("bar.sync %0, 64;" :: "r"(1 + seq) : "memory");

    // ---- tail (warp A only): mean + out-proj via owT + shuffle ------------
    if (half == 0) {
        float m = 0.f;
        if (r < 30) {
#pragma unroll
            for (int t = 0; t < 32; t++) m += OS[t * 33 + r];
            m *= (1.f / 32.f);
        }
        float emb = (r < 30) ? ob_s[r] : 0.f;
#pragma unroll
        for (int c = 0; c < 30; c++) {
            float mc = __shfl_sync(0xffffffffu, m, c);
            float wc = owT_s[c * 32 + r];
            emb = fmaf(mc, wc, emb);
        }
        if (r < 30) g_h1[sg * 30 + r] = emb;
    }
}

// ===========================================================================
// hop1 (unchanged from R10): single warp per sequence, S=17.
// Per-seq scratch 2016 floats.
// ===========================================================================
#define BUFF 2016

template <int S, bool FULL>
__device__ __forceinline__ float run_layer(int r,
                                           const float* __restrict__ xrow,
                                           const float* __restrict__ sm,
                                           float* __restrict__ buf,
                                           float invS) {
    const float* lw_s  = sm;
    const float* iw_s  = sm + 960;
    const float* owT_s = sm + 3840;
    const float* lb_s  = sm + 4800;
    const float* ib_s  = sm + 4832;
    const float* ob_s  = sm + 4928;
    const bool act = FULL || (r < S);

    ulonglong2* KA  = (ulonglong2*)buf;
    u64*        KV4 = (u64*)(buf + 384);
    ulonglong2* VA  = (ulonglong2*)(buf + 576);
    float*      OS  = buf + 960;          // [32][33]

    u64 yp[16];
    if (act) stage1_one(xrow, lw_s, lb_s, yp);

#pragma unroll 1
    for (int g = 0; g < 2; g++) {
        u64 q01[3], q23[3];
        float q4[3];
        if (act) {
#pragma unroll
            for (int j = 0; j < 3; j++) {
                const int h = g * 3 + j;
                float a0 = ib_s[h * 5 + 0] + dotp(iw_s + (h * 5 + 0) * 32, yp);
                float a1 = ib_s[h * 5 + 1] + dotp(iw_s + (h * 5 + 1) * 32, yp);
                float a2 = ib_s[h * 5 + 2] + dotp(iw_s + (h * 5 + 2) * 32, yp);
                float a3 = ib_s[h * 5 + 3] + dotp(iw_s + (h * 5 + 3) * 32, yp);
                float a4 = ib_s[h * 5 + 4] + dotp(iw_s + (h * 5 + 4) * 32, yp);
                q01[j] = pk2(a0, a1); q23[j] = pk2(a2, a3); q4[j] = a4;

                float k0 = ib_s[30 + h * 5 + 0] + dotp(iw_s + (30 + h * 5 + 0) * 32, yp);
                float k1 = ib_s[30 + h * 5 + 1] + dotp(iw_s + (30 + h * 5 + 1) * 32, yp);
                float k2 = ib_s[30 + h * 5 + 2] + dotp(iw_s + (30 + h * 5 + 2) * 32, yp);
                float k3 = ib_s[30 + h * 5 + 3] + dotp(iw_s + (30 + h * 5 + 3) * 32, yp);
                float k4 = ib_s[30 + h * 5 + 4] + dotp(iw_s + (30 + h * 5 + 4) * 32, yp);
                float v0 = ib_s[60 + h * 5 + 0] + dotp(iw_s + (60 + h * 5 + 0) * 32, yp);
                float v1 = ib_s[60 + h * 5 + 1] + dotp(iw_s + (60 + h * 5 + 1) * 32, yp);
                float v2 = ib_s[60 + h * 5 + 2] + dotp(iw_s + (60 + h * 5 + 2) * 32, yp);
                float v3 = ib_s[60 + h * 5 + 3] + dotp(iw_s + (60 + h * 5 + 3) * 32, yp);
                float v4 = ib_s[60 + h * 5 + 4] + dotp(iw_s + (60 + h * 5 + 4) * 32, yp);

                ulonglong2 kk; kk.x = pk2(k0, k1); kk.y = pk2(k2, k3);
                KA[j * 32 + r]  = kk;
                KV4[j * 32 + r] = pk2(k4, v4);
                ulonglong2 vv; vv.x = pk2(v0, v1); vv.y = pk2(v2, v3);
                VA[j * 32 + r]  = vv;
            }
        }
        __syncwarp();
        if (act) {
#pragma unroll
            for (int j = 0; j < 3; j++) {
                const int h = g * 3 + j;
                u64 a01 = 0ull, a23 = 0ull;
                float a4 = 0.f, es = 0.f;
#pragma unroll 8
                for (int t = 0; t < S; t++) {
                    ulonglong2 ka = KA[j * 32 + t];
                    float2 kv4 = upk2(KV4[j * 32 + t]);
                    u64 s2 = f2fma(ka.x, q01[j], f2fma(ka.y, q23[j], 0ull));
                    float2 sp = upk2(s2);
                    float e = ex2f(fmaf(q4[j], kv4.x, sp.x + sp.y));
                    u64 ee = pk2(e, e);
                    ulonglong2 va = VA[j * 32 + t];
                    a01 = f2fma(ee, va.x, a01);
                    a23 = f2fma(ee, va.y, a23);
                    a4  = fmaf(e, kv4.y, a4);
                    es += e;
                }
                float inv = rcpf(es);
                float2 p01 = upk2(a01), p23 = upk2(a23);
                float* os = OS + r * 33 + h * 5;
                os[0] = p01.x * inv;
                os[1] = p01.y * inv;
                os[2] = p23.x * inv;
                os[3] = p23.y * inv;
                os[4] = a4 * inv;
            }
        }
        __syncwarp();
    }

    float m = 0.f;
    if (r < 30) {
#pragma unroll
        for (int t = 0; t < S; t++) m += OS[t * 33 + r];
        m *= invS;
    }
    float emb = (r < 30) ? ob_s[r] : 0.f;
#pragma unroll
    for (int c = 0; c < 30; c++) {
        float mc = __shfl_sync(0xffffffffu, m, c);
        float wc = owT_s[c * 32 + r];
        emb = fmaf(mc, wc, emb);
    }
    return emb;
}

// ===========================================================================
// hop1: 6 nodes/CTA (192 thr) + classifier MLP + 2-class softmax (guarded).
// ===========================================================================
#define WPC1 6
#define OFF_CW1P (4960 + WPC1 * BUFF)    // 17056
#define OFF_CB1  (OFF_CW1P + 64 * 31)    // 19040
#define OFF_CW2P (OFF_CB1 + 64)          // 19104
#define OFF_CB2  (OFF_CW2P + 64 * 65)    // 23264
#define OFF_CW3  (OFF_CB2 + 64)          // 23328
#define OFF_CB3  (OFF_CW3 + 128)         // 23456
#define OFF_EMB  (OFF_CB3 + 4)           // 23460
#define OFF_HA   (OFF_EMB + WPC1 * 32)   // 23652
#define OFF_HB   (OFF_HA + WPC1 * 64)    // 24036
#define SMEM2_FLOATS (OFF_HB + WPC1 * 64)  // 24420 -> 97,680 B

__global__ void __launch_bounds__(192, 2) hop1_kernel(
    const float* __restrict__ self_feat,
    const float* __restrict__ lw, const float* __restrict__ lb,
    const float* __restrict__ iw, const float* __restrict__ ib,
    const float* __restrict__ ow, const float* __restrict__ ob,
    const float* __restrict__ cw1, const float* __restrict__ cb1,
    const float* __restrict__ cw2, const float* __restrict__ cb2,
    const float* __restrict__ cw3, const float* __restrict__ cb3,
    float* __restrict__ out) {
    extern __shared__ float sm[];
    const int tid = threadIdx.x;
    stage_weights(sm, tid, 192, lw, lb, iw, ib, ow, ob);
    float* cw1p = sm + OFF_CW1P;
    float* cb1s = sm + OFF_CB1;
    float* cw2p = sm + OFF_CW2P;
    float* cb2s = sm + OFF_CB2;
    float* cw3s = sm + OFF_CW3;
    float* cb3s = sm + OFF_CB3;
    float* embS = sm + OFF_EMB;
    float* hA   = sm + OFF_HA;
    float* hB   = sm + OFF_HB;
    for (int i = tid; i < 64 * 31; i += 192) {
        int row = i / 31, c = i % 31;
        cw1p[i] = (c < 30) ? cw1[row * 30 + c] : 0.f;
    }
    for (int i = tid; i < 64 * 65; i += 192) {
        int row = i / 65, c = i % 65;
        cw2p[i] = (c < 64) ? cw2[row * 64 + c] : 0.f;
    }
    if (tid < 64)  { cb1s[tid] = cb1[tid]; cb2s[tid] = cb2[tid]; }
    if (tid < 128) cw3s[tid] = cw3[tid];
    if (tid < 2)   cb3s[tid] = cb3[tid];
    __syncthreads();

    const int seq = tid >> 5, r = tid & 31;
    const int b = blockIdx.x * WPC1 + seq;
    if (b >= NB) return;
    float* buf = sm + 4960 + seq * BUFF;
    const float* xrow = (r < 16) ? (g_h1 + ((long)b * 16 + r) * 30)
                                 : (self_feat + (long)b * 30);

    float m = run_layer<17, false>(r, xrow, sm, buf, 1.f / 17.f);
    if (r < 30) embS[seq * 32 + r] = m;
    __syncwarp();

    // ---- classifier MLP (per warp) ----------------------------------------
    const float* emb = embS + seq * 32;
#pragma unroll
    for (int half = 0; half < 2; half++) {
        int j = r + 32 * half;
        float acc = cb1s[j];
#pragma unroll
        for (int k = 0; k < 30; k++) acc += emb[k] * cw1p[j * 31 + k];
        hA[seq * 64 + j] = fmaxf(acc, NEG * acc);
    }
    __syncwarp();
#pragma unroll
    for (int half = 0; half < 2; half++) {
        int j = r + 32 * half;
        float acc = cb2s[j];
#pragma unroll
        for (int k = 0; k < 64; k++) acc += hA[seq * 64 + k] * cw2p[j * 65 + k];
        hB[seq * 64 + j] = fmaxf(acc, NEG * acc);
    }
    __syncwarp();
    if (r < 2) {
        float acc = cb3s[r];
#pragma unroll
        for (int k = 0; k < 64; k++) acc += hB[seq * 64 + k] * cw3s[r * 64 + k];
        embS[seq * 32 + 30 + r] = acc;
    }
    __syncwarp();
    if (r == 0) {
        float l0 = embS[seq * 32 + 30], l1 = embS[seq * 32 + 31];
        float mx = fmaxf(l0, l1);
        float e0 = __expf(l0 - mx), e1 = __expf(l1 - mx);
        float inv = 1.f / (e0 + e1);
        out[(long)b * 2 + 0] = e0 * inv;
        out[(long)b * 2 + 1] = e1 * inv;
    }
}

// ===========================================================================
extern "C" void kernel_launch(void* const* d_in, const int* in_sizes, int n_in,
                              void* d_out, int out_size) {
    const float* x2   = (const float*)d_in[0];
    const float* self = (const float*)d_in[1];
    const float* lw2  = (const float*)d_in[2];
    const float* lb2  = (const float*)d_in[3];
    const float* iw2  = (const float*)d_in[4];
    const float* ib2  = (const float*)d_in[5];
    const float* ow2  = (const float*)d_in[6];
    const float* ob2  = (const float*)d_in[7];
    const float* lw1  = (const float*)d_in[8];
    const float* lb1  = (const float*)d_in[9];
    const float* iw1  = (const float*)d_in[10];
    const float* ib1  = (const float*)d_in[11];
    const float* ow1  = (const float*)d_in[12];
    const float* ob1  = (const float*)d_in[13];
    const float* cw1  = (const float*)d_in[14];
    const float* cb1  = (const float*)d_in[15];
    const float* cw2  = (const float*)d_in[16];
    const float* cb2  = (const float*)d_in[17];
    const float* cw3  = (const float*)d_in[18];
    const float* cb3  = (const float*)d_in[19];
    float* out = (float*)d_out;

    const int smem1 = SMEM1_FLOATS * 4;
    const int smem2 = SMEM2_FLOATS * 4;
    cudaFuncSetAttribute(hop2_kernel,
                         cudaFuncAttributeMaxDynamicSharedMemorySize, smem1);
    cudaFuncSetAttribute(hop1_kernel,
                         cudaFuncAttributeMaxDynamicSharedMemorySize, smem2);

    hop2_kernel<<<NSEQ2 / SPC, 256, smem1>>>(x2, lw2, lb2, iw2, ib2, ow2, ob2);
    hop1_kernel<<<(NB + WPC1 - 1) / WPC1, 192, smem2>>>(
        self, lw1, lb1, iw1, ib1, ow1, ob1,
        cw1, cb1, cw2, cb2, cw3, cb3, out);
}

// round 13
// speedup vs baseline: 1.1591x; 1.1591x over previous
#include <cuda_runtime.h>

#define NB 4096
#define NEG 0.02f
// (1/sqrt(5)) * log2(e)
#define CEXP 0.6451928329f

typedef unsigned long long u64;

// hop-2 output: [B*N1, 30]
__device__ float g_h1[NB * 16 * 30];

// ---------------------------------------------------------------------------
__device__ __forceinline__ u64 pk2(float lo, float hi) {
    u64 v; asm("mov.b64 %0,{%1,%2};" : "=l"(v) : "f"(lo), "f"(hi)); return v;
}
__device__ __forceinline__ float2 upk2(u64 v) {
    float2 r; asm("mov.b64 {%0,%1},%2;" : "=f"(r.x), "=f"(r.y) : "l"(v)); return r;
}
__device__ __forceinline__ u64 f2fma(u64 a, u64 b, u64 c) {
    u64 d; asm("fma.rn.f32x2 %0,%1,%2,%3;" : "=l"(d) : "l"(a), "l"(b), "l"(c));
    return d;
}
__device__ __forceinline__ u64 f2add(u64 a, u64 b) {
    u64 d; asm("add.rn.f32x2 %0,%1,%2;" : "=l"(d) : "l"(a), "l"(b));
    return d;
}
__device__ __forceinline__ float ex2f(float x) {
    float r; asm("ex2.approx.f32 %0,%1;" : "=f"(r) : "f"(x)); return r;
}
__device__ __forceinline__ float rcpf(float x) {
    float r; asm("rcp.approx.f32 %0,%1;" : "=f"(r) : "f"(x)); return r;
}

// packed dot (hop1 path only), 4 accumulators
__device__ __forceinline__ float dotp(const float* __restrict__ wrow,
                                      const u64 (&v)[16]) {
    const ulonglong2* w2 = (const ulonglong2*)wrow;
    u64 a0 = 0ull, a1 = 0ull, a2 = 0ull, a3 = 0ull;
#pragma unroll
    for (int kk = 0; kk < 2; kk++) {
        ulonglong2 wa = w2[4 * kk + 0];
        ulonglong2 wb = w2[4 * kk + 1];
        ulonglong2 wc = w2[4 * kk + 2];
        ulonglong2 wd = w2[4 * kk + 3];
        a0 = f2fma(wa.x, v[8 * kk + 0], a0);
        a1 = f2fma(wa.y, v[8 * kk + 1], a1);
        a2 = f2fma(wb.x, v[8 * kk + 2], a2);
        a3 = f2fma(wb.y, v[8 * kk + 3], a3);
        a0 = f2fma(wc.x, v[8 * kk + 4], a0);
        a1 = f2fma(wc.y, v[8 * kk + 5], a1);
        a2 = f2fma(wd.x, v[8 * kk + 6], a2);
        a3 = f2fma(wd.y, v[8 * kk + 7], a3);
    }
    u64 s = f2add(f2add(a0, a1), f2add(a2, a3));
    float2 f = upk2(s);
    return f.x + f.y;
}

// stage1 (hop1 path only)
__device__ __forceinline__ void stage1_one(const float* __restrict__ xrow,
                                           const float* __restrict__ lw_s,
                                           const float* __restrict__ lb_s,
                                           u64 (&yp)[16]) {
    u64 xp[16];
#pragma unroll
    for (int k = 0; k < 15; k++) {
        float2 t = *(const float2*)(xrow + 2 * k);
        xp[k] = pk2(t.x, t.y);
    }
    xp[15] = 0ull;
#pragma unroll
    for (int jj = 0; jj < 15; jj++) {
        float y0 = lb_s[2 * jj]     + dotp(lw_s + (2 * jj) * 32, xp);
        float y1 = lb_s[2 * jj + 1] + dotp(lw_s + (2 * jj + 1) * 32, xp);
        y0 = fmaxf(y0, NEG * y0);
        y1 = fmaxf(y1, NEG * y1);
        yp[jj] = pk2(y0, y1);
    }
    yp[15] = 0ull;
}

// ===========================================================================
// hop2 weight staging (outer-product layout):
//   lwT  [0,960):     lwT[k*32+j] = lw[j][k]            (j<30, pad 0)
//   qkvT [960,3840):  six 480-blocks, order qT0 kT0 vT0 qT1 kT1 vT1,
//                     block[k*16+jj] = iw[which*30 + g*15 + jj][k]
//                     (q blocks pre-scaled by CEXP)
//   owT  [3840,4800): owT[c*32+j] = ow[j][c]
//   lb   @4800(32) | qb0@4832 kb0@4848 vb0@4864 qb1@4880 kb1@4896 vb1@4912
//   ob   @4928(32)
// ===========================================================================
__device__ __forceinline__ void stage_weights2(float* sm, int tid,
                                               const float* lw, const float* lb,
                                               const float* iw, const float* ib,
                                               const float* ow, const float* ob) {
    for (int i = tid; i < 960; i += 256) {
        int k = i >> 5, j = i & 31;
        sm[i] = (j < 30) ? lw[j * 30 + k] : 0.f;
    }
    for (int i = tid; i < 2880; i += 256) {
        int blk = i / 480, rem = i % 480;
        int k = rem >> 4, jj = rem & 15;
        int g = blk / 3, which = blk % 3;   // 0=q,1=k,2=v
        float v = 0.f;
        if (jj < 15) {
            v = iw[(which * 30 + g * 15 + jj) * 30 + k];
            if (which == 0) v *= CEXP;
        }
        sm[960 + i] = v;
    }
    for (int i = tid; i < 960; i += 256) {
        int c = i >> 5, j = i & 31;
        sm[3840 + i] = (j < 30) ? ow[j * 30 + c] : 0.f;
    }
    if (tid < 32) sm[4800 + tid] = (tid < 30) ? lb[tid] : 0.f;
    if (tid < 16) sm[4832 + tid] = (tid < 15) ? ib[tid] * CEXP : 0.f;
    if (tid < 16) sm[4848 + tid] = (tid < 15) ? ib[30 + tid] : 0.f;
    if (tid < 16) sm[4864 + tid] = (tid < 15) ? ib[60 + tid] : 0.f;
    if (tid < 16) sm[4880 + tid] = (tid < 15) ? ib[15 + tid] * CEXP : 0.f;
    if (tid < 16) sm[4896 + tid] = (tid < 15) ? ib[45 + tid] : 0.f;
    if (tid < 16) sm[4912 + tid] = (tid < 15) ? ib[75 + tid] : 0.f;
    if (tid < 32) sm[4928 + tid] = (tid < 30) ? ob[tid] : 0.f;
}

// extract 3 heads' (d0,d1),(d2,d3),d4 from a 15-wide pair-accumulator
__device__ __forceinline__ void extract3(const u64 (&A)[8],
                                         u64 (&p01)[3], u64 (&p23)[3],
                                         float (&s4)[3]) {
    p01[0] = A[0]; p23[0] = A[1];
    float2 a2 = upk2(A[2]), a3 = upk2(A[3]), a4 = upk2(A[4]);
    s4[0] = a2.x;
    p01[1] = pk2(a2.y, a3.x);
    p23[1] = pk2(a3.y, a4.x);
    s4[1] = a4.y;
    p01[2] = A[5]; p23[2] = A[6];
    float2 a7 = upk2(A[7]);
    s4[2] = a7.x;
}

// ===========================================================================
// hop2: 8 seq/CTA (one per warp), outer-product formulation.
// Per-seq scratch 2016 floats (R10 layout):
//   KA u2[96] [0,384) | KV4 u64[96] [384,576) | VA u2[96] [576,960)
//   OS float[32][33] [960,2016)
// ===========================================================================
#define BUFF 2016
#define WPC2 8
#define NSEQ2 (NB * 16)
#define SMEM1_FLOATS (4960 + WPC2 * BUFF)    // 21088 -> 84,352 B

__global__ void __launch_bounds__(256, 2) hop2_kernel(
    const float* __restrict__ x2,
    const float* __restrict__ lw, const float* __restrict__ lb,
    const float* __restrict__ iw, const float* __restrict__ ib,
    const float* __restrict__ ow, const float* __restrict__ ob) {
    extern __shared__ float sm[];
    const int tid = threadIdx.x;
    stage_weights2(sm, tid, lw, lb, iw, ib, ow, ob);
    __syncthreads();

    const float* owT_s = sm + 3840;
    const float* ob_s  = sm + 4928;

    const int seq = tid >> 5, r = tid & 31;
    const long sg = (long)blockIdx.x * WPC2 + seq;
    float* buf = sm + 4960 + seq * BUFF;

    ulonglong2* KA  = (ulonglong2*)buf;
    u64*        KV4 = (u64*)(buf + 384);
    ulonglong2* VA  = (ulonglong2*)(buf + 576);
    float*      OS  = buf + 960;          // [32][33]

    // ---- stage 1: outer-product 30x30, bias-initialized -------------------
    float x[30];
    {
        const float* xp = x2 + (sg * 32 + r) * 30;
#pragma unroll
        for (int k2 = 0; k2 < 15; k2++) {
            float2 t = *(const float2*)(xp + 2 * k2);
            x[2 * k2] = t.x; x[2 * k2 + 1] = t.y;
        }
    }
    float y[30];
    {
        u64 acc[15];
        const u64* bp = (const u64*)(sm + 4800);
#pragma unroll
        for (int p = 0; p < 15; p++) acc[p] = bp[p];
#pragma unroll
        for (int k = 0; k < 30; k++) {
            const ulonglong2* w2 = (const ulonglong2*)(sm + k * 32);
            u64 sd = pk2(x[k], x[k]);
#pragma unroll
            for (int p = 0; p < 7; p++) {
                ulonglong2 ww = w2[p];
                acc[2 * p]     = f2fma(ww.x, sd, acc[2 * p]);
                acc[2 * p + 1] = f2fma(ww.y, sd, acc[2 * p + 1]);
            }
            u64 wl = *(const u64*)(sm + k * 32 + 28);
            acc[14] = f2fma(wl, sd, acc[14]);
        }
#pragma unroll
        for (int p = 0; p < 15; p++) {
            float2 v = upk2(acc[p]);
            y[2 * p]     = fmaxf(v.x, NEG * v.x);
            y[2 * p + 1] = fmaxf(v.y, NEG * v.y);
        }
    }

    // ---- head groups of 3: fused qkv outer-product -> stage -> attention --
#pragma unroll 1
    for (int g = 0; g < 2; g++) {
        const float* qT = sm + 960 + g * 1440;
        const float* kT = qT + 480;
        const float* vT = kT + 480;
        const u64* qb = (const u64*)(sm + 4832 + g * 48);
        const u64* kb = (const u64*)(sm + 4848 + g * 48);
        const u64* vb = (const u64*)(sm + 4864 + g * 48);

        u64 qa[8], ka[8], va[8];
#pragma unroll
        for (int p = 0; p < 8; p++) { qa[p] = qb[p]; ka[p] = kb[p]; va[p] = vb[p]; }
#pragma unroll
        for (int k = 0; k < 30; k++) {
            u64 sd = pk2(y[k], y[k]);
            const ulonglong2* wq = (const ulonglong2*)(qT + k * 16);
            const ulonglong2* wk = (const ulonglong2*)(kT + k * 16);
            const ulonglong2* wv = (const ulonglong2*)(vT + k * 16);
#pragma unroll
            for (int p = 0; p < 4; p++) {
                ulonglong2 a = wq[p];
                qa[2 * p]     = f2fma(a.x, sd, qa[2 * p]);
                qa[2 * p + 1] = f2fma(a.y, sd, qa[2 * p + 1]);
                ulonglong2 b = wk[p];
                ka[2 * p]     = f2fma(b.x, sd, ka[2 * p]);
                ka[2 * p + 1] = f2fma(b.y, sd, ka[2 * p + 1]);
                ulonglong2 c = wv[p];
                va[2 * p]     = f2fma(c.x, sd, va[2 * p]);
                va[2 * p + 1] = f2fma(c.y, sd, va[2 * p + 1]);
            }
        }

        u64 q01[3], q23[3]; float q4[3];
        extract3(qa, q01, q23, q4);
        u64 kp01[3], kp23[3]; float k4s[3];
        extract3(ka, kp01, kp23, k4s);
        u64 vp01[3], vp23[3]; float v4s[3];
        extract3(va, vp01, vp23, v4s);

#pragma unroll
        for (int j = 0; j < 3; j++) {
            ulonglong2 kk; kk.x = kp01[j]; kk.y = kp23[j];
            KA[j * 32 + r]  = kk;
            KV4[j * 32 + r] = pk2(k4s[j], v4s[j]);
            ulonglong2 vv; vv.x = vp01[j]; vv.y = vp23[j];
            VA[j * 32 + r]  = vv;
        }
        __syncwarp();

#pragma unroll
        for (int j = 0; j < 3; j++) {
            const int h = g * 3 + j;
            u64 a01 = 0ull, a23 = 0ull;
            float a4 = 0.f, es = 0.f;
#pragma unroll 8
            for (int t = 0; t < 32; t++) {
                ulonglong2 ka2 = KA[j * 32 + t];
                float2 kv4 = upk2(KV4[j * 32 + t]);
                u64 s2 = f2fma(ka2.x, q01[j], f2fma(ka2.y, q23[j], 0ull));
                float2 sp = upk2(s2);
                float e = ex2f(fmaf(q4[j], kv4.x, sp.x + sp.y));
                u64 ee = pk2(e, e);
                ulonglong2 va2 = VA[j * 32 + t];
                a01 = f2fma(ee, va2.x, a01);
                a23 = f2fma(ee, va2.y, a23);
                a4  = fmaf(e, kv4.y, a4);
                es += e;
            }
            float inv = rcpf(es);
            float2 p01 = upk2(a01), p23 = upk2(a23);
            float* os = OS + r * 33 + h * 5;
            os[0] = p01.x * inv;
            os[1] = p01.y * inv;
            os[2] = p23.x * inv;
            os[3] = p23.y * inv;
            os[4] = a4 * inv;
        }
        __syncwarp();   // protects K/V rewrite (g=0) and OS-before-mean (g=1)
    }

    // ---- column mean + out-proj via owT + shuffle -------------------------
    float m = 0.f;
    if (r < 30) {
#pragma unroll
        for (int t = 0; t < 32; t++) m += OS[t * 33 + r];
        m *= (1.f / 32.f);
    }
    float emb = (r < 30) ? ob_s[r] : 0.f;
#pragma unroll
    for (int c = 0; c < 30; c++) {
        float mc = __shfl_sync(0xffffffffu, m, c);
        float wc = owT_s[c * 32 + r];
        emb = fmaf(mc, wc, emb);
    }
    if (r < 30) g_h1[sg * 30 + r] = emb;
}

// ===========================================================================
// hop1 (unchanged R10 path): old weight layout + dotp run_layer.
// ===========================================================================
__device__ __forceinline__ void stage_weights1(float* sm, int tid, int nthr,
                                               const float* lw, const float* lb,
                                               const float* iw, const float* ib,
                                               const float* ow, const float* ob) {
    for (int i = tid; i < 4800; i += nthr) {
        int row = i >> 5, col = i & 31;
        float v = 0.f;
        if (col < 30) {
            if (row < 30)       v = lw[row * 30 + col];
            else if (row < 120) {
                v = iw[(row - 30) * 30 + col];
                if (row < 60) v *= CEXP;
            } else                v = ow[col * 30 + (row - 120)];  // owT
        }
        sm[i] = v;
    }
    if (tid < 30) sm[4800 + tid] = lb[tid];
    if (tid < 90) sm[4832 + tid] = (tid < 30) ? ib[tid] * CEXP : ib[tid];
    if (tid < 32) sm[4928 + tid] = (tid < 30) ? ob[tid] : 0.f;
}

template <int S, bool FULL>
__device__ __forceinline__ float run_layer(int r,
                                           const float* __restrict__ xrow,
                                           const float* __restrict__ sm,
                                           float* __restrict__ buf,
                                           float invS) {
    const float* lw_s  = sm;
    const float* iw_s  = sm + 960;
    const float* owT_s = sm + 3840;
    const float* lb_s  = sm + 4800;
    const float* ib_s  = sm + 4832;
    const float* ob_s  = sm + 4928;
    const bool act = FULL || (r < S);

    ulonglong2* KA  = (ulonglong2*)buf;
    u64*        KV4 = (u64*)(buf + 384);
    ulonglong2* VA  = (ulonglong2*)(buf + 576);
    float*      OS  = buf + 960;          // [32][33]

    u64 yp[16];
    if (act) stage1_one(xrow, lw_s, lb_s, yp);

#pragma unroll 1
    for (int g = 0; g < 2; g++) {
        u64 q01[3], q23[3];
        float q4[3];
        if (act) {
#pragma unroll
            for (int j = 0; j < 3; j++) {
                const int h = g * 3 + j;
                float a0 = ib_s[h * 5 + 0] + dotp(iw_s + (h * 5 + 0) * 32, yp);
                float a1 = ib_s[h * 5 + 1] + dotp(iw_s + (h * 5 + 1) * 32, yp);
                float a2 = ib_s[h * 5 + 2] + dotp(iw_s + (h * 5 + 2) * 32, yp);
                float a3 = ib_s[h * 5 + 3] + dotp(iw_s + (h * 5 + 3) * 32, yp);
                float a4 = ib_s[h * 5 + 4] + dotp(iw_s + (h * 5 + 4) * 32, yp);
                q01[j] = pk2(a0, a1); q23[j] = pk2(a2, a3); q4[j] = a4;

                float k0 = ib_s[30 + h * 5 + 0] + dotp(iw_s + (30 + h * 5 + 0) * 32, yp);
                float k1 = ib_s[30 + h * 5 + 1] + dotp(iw_s + (30 + h * 5 + 1) * 32, yp);
                float k2 = ib_s[30 + h * 5 + 2] + dotp(iw_s + (30 + h * 5 + 2) * 32, yp);
                float k3 = ib_s[30 + h * 5 + 3] + dotp(iw_s + (30 + h * 5 + 3) * 32, yp);
                float k4 = ib_s[30 + h * 5 + 4] + dotp(iw_s + (30 + h * 5 + 4) * 32, yp);
                float v0 = ib_s[60 + h * 5 + 0] + dotp(iw_s + (60 + h * 5 + 0) * 32, yp);
                float v1 = ib_s[60 + h * 5 + 1] + dotp(iw_s + (60 + h * 5 + 1) * 32, yp);
                float v2 = ib_s[60 + h * 5 + 2] + dotp(iw_s + (60 + h * 5 + 2) * 32, yp);
                float v3 = ib_s[60 + h * 5 + 3] + dotp(iw_s + (60 + h * 5 + 3) * 32, yp);
                float v4 = ib_s[60 + h * 5 + 4] + dotp(iw_s + (60 + h * 5 + 4) * 32, yp);

                ulonglong2 kk; kk.x = pk2(k0, k1); kk.y = pk2(k2, k3);
                KA[j * 32 + r]  = kk;
                KV4[j * 32 + r] = pk2(k4, v4);
                ulonglong2 vv; vv.x = pk2(v0, v1); vv.y = pk2(v2, v3);
                VA[j * 32 + r]  = vv;
            }
        }
        __syncwarp();
        if (act) {
#pragma unroll
            for (int j = 0; j < 3; j++) {
                const int h = g * 3 + j;
                u64 a01 = 0ull, a23 = 0ull;
                float a4 = 0.f, es = 0.f;
#pragma unroll 8
                for (int t = 0; t < S; t++) {
                    ulonglong2 ka = KA[j * 32 + t];
                    float2 kv4 = upk2(KV4[j * 32 + t]);
                    u64 s2 = f2fma(ka.x, q01[j], f2fma(ka.y, q23[j], 0ull));
                    float2 sp = upk2(s2);
                    float e = ex2f(fmaf(q4[j], kv4.x, sp.x + sp.y));
                    u64 ee = pk2(e, e);
                    ulonglong2 va = VA[j * 32 + t];
                    a01 = f2fma(ee, va.x, a01);
                    a23 = f2fma(ee, va.y, a23);
                    a4  = fmaf(e, kv4.y, a4);
                    es += e;
                }
                float inv = rcpf(es);
                float2 p01 = upk2(a01), p23 = upk2(a23);
                float* os = OS + r * 33 + h * 5;
                os[0] = p01.x * inv;
                os[1] = p01.y * inv;
                os[2] = p23.x * inv;
                os[3] = p23.y * inv;
                os[4] = a4 * inv;
            }
        }
        __syncwarp();
    }

    float m = 0.f;
    if (r < 30) {
#pragma unroll
        for (int t = 0; t < S; t++) m += OS[t * 33 + r];
        m *= invS;
    }
    float emb = (r < 30) ? ob_s[r] : 0.f;
#pragma unroll
    for (int c = 0; c < 30; c++) {
        float mc = __shfl_sync(0xffffffffu, m, c);
        float wc = owT_s[c * 32 + r];
        emb = fmaf(mc, wc, emb);
    }
    return emb;
}

// ===========================================================================
// hop1: 6 nodes/CTA (192 thr) + classifier MLP + 2-class softmax (guarded).
// ===========================================================================
#define WPC1 6
#define OFF_CW1P (4960 + WPC1 * BUFF)    // 17056
#define OFF_CB1  (OFF_CW1P + 64 * 31)    // 19040
#define OFF_CW2P (OFF_CB1 + 64)          // 19104
#define OFF_CB2  (OFF_CW2P + 64 * 65)    // 23264
#define OFF_CW3  (OFF_CB2 + 64)          // 23328
#define OFF_CB3  (OFF_CW3 + 128)         // 23456
#define OFF_EMB  (OFF_CB3 + 4)           // 23460
#define OFF_HA   (OFF_EMB + WPC1 * 32)   // 23652
#define OFF_HB   (OFF_HA + WPC1 * 64)    // 24036
#define SMEM2_FLOATS (OFF_HB + WPC1 * 64)  // 24420 -> 97,680 B

__global__ void __launch_bounds__(192, 2) hop1_kernel(
    const float* __restrict__ self_feat,
    const float* __restrict__ lw, const float* __restrict__ lb,
    const float* __restrict__ iw, const float* __restrict__ ib,
    const float* __restrict__ ow, const float* __restrict__ ob,
    const float* __restrict__ cw1, const float* __restrict__ cb1,
    const float* __restrict__ cw2, const float* __restrict__ cb2,
    const float* __restrict__ cw3, const float* __restrict__ cb3,
    float* __restrict__ out) {
    extern __shared__ float sm[];
    const int tid = threadIdx.x;
    stage_weights1(sm, tid, 192, lw, lb, iw, ib, ow, ob);
    float* cw1p = sm + OFF_CW1P;
    float* cb1s = sm + OFF_CB1;
    float* cw2p = sm + OFF_CW2P;
    float* cb2s = sm + OFF_CB2;
    float* cw3s = sm + OFF_CW3;
    float* cb3s = sm + OFF_CB3;
    float* embS = sm + OFF_EMB;
    float* hA   = sm + OFF_HA;
    float* hB   = sm + OFF_HB;
    for (int i = tid; i < 64 * 31; i += 192) {
        int row = i / 31, c = i % 31;
        cw1p[i] = (c < 30) ? cw1[row * 30 + c] : 0.f;
    }
    for (int i = tid; i < 64 * 65; i += 192) {
        int row = i / 65, c = i % 65;
        cw2p[i] = (c < 64) ? cw2[row * 64 + c] : 0.f;
    }
    if (tid < 64)  { cb1s[tid] = cb1[tid]; cb2s[tid] = cb2[tid]; }
    if (tid < 128) cw3s[tid] = cw3[tid];
    if (tid < 2)   cb3s[tid] = cb3[tid];
    __syncthreads();

    const int seq = tid >> 5, r = tid & 31;
    const int b = blockIdx.x * WPC1 + seq;
    if (b >= NB) return;
    float* buf = sm + 4960 + seq * BUFF;
    const float* xrow = (r < 16) ? (g_h1 + ((long)b * 16 + r) * 30)
                                 : (self_feat + (long)b * 30);

    float m = run_layer<17, false>(r, xrow, sm, buf, 1.f / 17.f);
    if (r < 30) embS[seq * 32 + r] = m;
    __syncwarp();

    // ---- classifier MLP (per warp) ----------------------------------------
    const float* emb = embS + seq * 32;
#pragma unroll
    for (int half = 0; half < 2; half++) {
        int j = r + 32 * half;
        float acc = cb1s[j];
#pragma unroll
        for (int k = 0; k < 30; k++) acc += emb[k] * cw1p[j * 31 + k];
        hA[seq * 64 + j] = fmaxf(acc, NEG * acc);
    }
    __syncwarp();
#pragma unroll
    for (int half = 0; half < 2; half++) {
        int j = r + 32 * half;
        float acc = cb2s[j];
#pragma unroll
        for (int k = 0; k < 64; k++) acc += hA[seq * 64 + k] * cw2p[j * 65 + k];
        hB[seq * 64 + j] = fmaxf(acc, NEG * acc);
    }
    __syncwarp();
    if (r < 2) {
        float acc = cb3s[r];
#pragma unroll
        for (int k = 0; k < 64; k++) acc += hB[seq * 64 + k] * cw3s[r * 64 + k];
        embS[seq * 32 + 30 + r] = acc;
    }
    __syncwarp();
    if (r == 0) {
        float l0 = embS[seq * 32 + 30], l1 = embS[seq * 32 + 31];
        float mx = fmaxf(l0, l1);
        float e0 = __expf(l0 - mx), e1 = __expf(l1 - mx);
        float inv = 1.f / (e0 + e1);
        out[(long)b * 2 + 0] = e0 * inv;
        out[(long)b * 2 + 1] = e1 * inv;
    }
}

// ===========================================================================
extern "C" void kernel_launch(void* const* d_in, const int* in_sizes, int n_in,
                              void* d_out, int out_size) {
    const float* x2   = (const float*)d_in[0];
    const float* self = (const float*)d_in[1];
    const float* lw2  = (const float*)d_in[2];
    const float* lb2  = (const float*)d_in[3];
    const float* iw2  = (const float*)d_in[4];
    const float* ib2  = (const float*)d_in[5];
    const float* ow2  = (const float*)d_in[6];
    const float* ob2  = (const float*)d_in[7];
    const float* lw1  = (const float*)d_in[8];
    const float* lb1  = (const float*)d_in[9];
    const float* iw1  = (const float*)d_in[10];
    const float* ib1  = (const float*)d_in[11];
    const float* ow1  = (const float*)d_in[12];
    const float* ob1  = (const float*)d_in[13];
    const float* cw1  = (const float*)d_in[14];
    const float* cb1  = (const float*)d_in[15];
    const float* cw2  = (const float*)d_in[16];
    const float* cb2  = (const float*)d_in[17];
    const float* cw3  = (const float*)d_in[18];
    const float* cb3  = (const float*)d_in[19];
    float* out = (float*)d_out;

    const int smem1 = SMEM1_FLOATS * 4;
    const int smem2 = SMEM2_FLOATS * 4;
    cudaFuncSetAttribute(hop2_kernel,
                         cudaFuncAttributeMaxDynamicSharedMemorySize, smem1);
    cudaFuncSetAttribute(hop1_kernel,
                         cudaFuncAttributeMaxDynamicSharedMemorySize, smem2);

    hop2_kernel<<<NSEQ2 / WPC2, 256, smem1>>>(x2, lw2, lb2, iw2, ib2, ow2, ob2);
    hop1_kernel<<<(NB + WPC1 - 1) / WPC1, 192, smem2>>>(
        self, lw1, lb1, iw1, ib1, ow1, ob1,
        cw1, cb1, cw2, cb2, cw3, cb3, out);
}

// round 15
// speedup vs baseline: 1.2069x; 1.0412x over previous
#include <cuda_runtime.h>

#define NB 4096
#define NEG 0.02f
// (1/sqrt(5)) * log2(e)
#define CEXP 0.6451928329f

typedef unsigned long long u64;

// hop-2 output: [B*N1, 30]
__device__ float g_h1[NB * 16 * 30];

// ---------------------------------------------------------------------------
__device__ __forceinline__ u64 pk2(float lo, float hi) {
    u64 v; asm("mov.b64 %0,{%1,%2};" : "=l"(v) : "f"(lo), "f"(hi)); return v;
}
__device__ __forceinline__ float2 upk2(u64 v) {
    float2 r; asm("mov.b64 {%0,%1},%2;" : "=f"(r.x), "=f"(r.y) : "l"(v)); return r;
}
__device__ __forceinline__ u64 f2fma(u64 a, u64 b, u64 c) {
    u64 d; asm("fma.rn.f32x2 %0,%1,%2,%3;" : "=l"(d) : "l"(a), "l"(b), "l"(c));
    return d;
}
__device__ __forceinline__ u64 f2add(u64 a, u64 b) {
    u64 d; asm("add.rn.f32x2 %0,%1,%2;" : "=l"(d) : "l"(a), "l"(b));
    return d;
}
__device__ __forceinline__ float ex2f(float x) {
    float r; asm("ex2.approx.f32 %0,%1;" : "=f"(r) : "f"(x)); return r;
}
__device__ __forceinline__ float rcpf(float x) {
    float r; asm("rcp.approx.f32 %0,%1;" : "=f"(r) : "f"(x)); return r;
}

// packed dot, 4 accumulators: 32-float weight row (pad zeroed) vs 16 u64
__device__ __forceinline__ float dotp(const float* __restrict__ wrow,
                                      const u64 (&v)[16]) {
    const ulonglong2* w2 = (const ulonglong2*)wrow;
    u64 a0 = 0ull, a1 = 0ull, a2 = 0ull, a3 = 0ull;
#pragma unroll
    for (int kk = 0; kk < 2; kk++) {
        ulonglong2 wa = w2[4 * kk + 0];
        ulonglong2 wb = w2[4 * kk + 1];
        ulonglong2 wc = w2[4 * kk + 2];
        ulonglong2 wd = w2[4 * kk + 3];
        a0 = f2fma(wa.x, v[8 * kk + 0], a0);
        a1 = f2fma(wa.y, v[8 * kk + 1], a1);
        a2 = f2fma(wb.x, v[8 * kk + 2], a2);
        a3 = f2fma(wb.y, v[8 * kk + 3], a3);
        a0 = f2fma(wc.x, v[8 * kk + 4], a0);
        a1 = f2fma(wc.y, v[8 * kk + 5], a1);
        a2 = f2fma(wd.x, v[8 * kk + 6], a2);
        a3 = f2fma(wd.y, v[8 * kk + 7], a3);
    }
    u64 s = f2add(f2add(a0, a1), f2add(a2, a3));
    float2 f = upk2(s);
    return f.x + f.y;
}

// stage1 for one sequence row: y = leaky(x @ lw^T + lb), packed result
__device__ __forceinline__ void stage1_one(const float* __restrict__ xrow,
                                           const float* __restrict__ lw_s,
                                           const float* __restrict__ lb_s,
                                           u64 (&yp)[16]) {
    u64 xp[16];
#pragma unroll
    for (int k = 0; k < 15; k++) {
        float2 t = *(const float2*)(xrow + 2 * k);
        xp[k] = pk2(t.x, t.y);
    }
    xp[15] = 0ull;
#pragma unroll
    for (int jj = 0; jj < 15; jj++) {
        float y0 = lb_s[2 * jj]     + dotp(lw_s + (2 * jj) * 32, xp);
        float y1 = lb_s[2 * jj + 1] + dotp(lw_s + (2 * jj + 1) * 32, xp);
        y0 = fmaxf(y0, NEG * y0);
        y1 = fmaxf(y1, NEG * y1);
        yp[jj] = pk2(y0, y1);
    }
    yp[15] = 0ull;
}

// ---------------------------------------------------------------------------
// sm layout: lw 0..959 | iw 960..3839 | owT 3840..4799 (TRANSPOSED) |
//            lb 4800 | ib 4832 | ob 4928..4959
//            (q-rows of iw and q-bias pre-scaled by CEXP)
// ---------------------------------------------------------------------------
__device__ __forceinline__ void stage_weights(float* sm, int tid, int nthr,
                                              const float* lw, const float* lb,
                                              const float* iw, const float* ib,
                                              const float* ow, const float* ob) {
    for (int i = tid; i < 4800; i += nthr) {
        int row = i >> 5, col = i & 31;
        float v = 0.f;
        if (col < 30) {
            if (row < 30)       v = lw[row * 30 + col];
            else if (row < 120) {
                v = iw[(row - 30) * 30 + col];
                if (row < 60) v *= CEXP;            // fold attn scale into q
            } else                v = ow[col * 30 + (row - 120)];  // owT
        }
        sm[i] = v;
    }
    if (tid < 30) sm[4800 + tid] = lb[tid];
    if (tid < 90) sm[4832 + tid] = (tid < 30) ? ib[tid] * CEXP : ib[tid];
    if (tid < 32) sm[4928 + tid] = (tid < 30) ? ob[tid] : 0.f;
}

// ===========================================================================
// One GraphLayer for one sequence per warp. Per-seq scratch 2016 floats:
//   KA  : ulonglong2[96] [0,384)    (k0..k3) per (head j in group, row t)
//   KV4 : u64[96]        [384,576)  (k4, v4) packed
//   VA  : ulonglong2[96] [576,960)  (v0..v3)
//   OS  : float[32][33]  [960,2016) per-row attention outputs o[30]
// ===========================================================================
#define BUFF 2016

template <int S, bool FULL>
__device__ __forceinline__ float run_layer(int r,
                                           const float* __restrict__ xrow,
                                           const float* __restrict__ sm,
                                           float* __restrict__ buf,
                                           float invS) {
    const float* lw_s  = sm;
    const float* iw_s  = sm + 960;
    const float* owT_s = sm + 3840;
    const float* lb_s  = sm + 4800;
    const float* ib_s  = sm + 4832;
    const float* ob_s  = sm + 4928;
    const bool act = FULL || (r < S);

    ulonglong2* KA  = (ulonglong2*)buf;
    u64*        KV4 = (u64*)(buf + 384);
    ulonglong2* VA  = (ulonglong2*)(buf + 576);
    float*      OS  = buf + 960;          // [32][33]

    u64 yp[16];
    if (act) stage1_one(xrow, lw_s, lb_s, yp);

    // ---- head groups of 3: qkv -> stage -> attention -> OS ----------------
#pragma unroll 1
    for (int g = 0; g < 2; g++) {
        u64 q01[3], q23[3];
        float q4[3];
        if (act) {
#pragma unroll
            for (int j = 0; j < 3; j++) {
                const int h = g * 3 + j;
                float a0 = ib_s[h * 5 + 0] + dotp(iw_s + (h * 5 + 0) * 32, yp);
                float a1 = ib_s[h * 5 + 1] + dotp(iw_s + (h * 5 + 1) * 32, yp);
                float a2 = ib_s[h * 5 + 2] + dotp(iw_s + (h * 5 + 2) * 32, yp);
                float a3 = ib_s[h * 5 + 3] + dotp(iw_s + (h * 5 + 3) * 32, yp);
                float a4 = ib_s[h * 5 + 4] + dotp(iw_s + (h * 5 + 4) * 32, yp);
                q01[j] = pk2(a0, a1); q23[j] = pk2(a2, a3); q4[j] = a4;

                float k0 = ib_s[30 + h * 5 + 0] + dotp(iw_s + (30 + h * 5 + 0) * 32, yp);
                float k1 = ib_s[30 + h * 5 + 1] + dotp(iw_s + (30 + h * 5 + 1) * 32, yp);
                float k2 = ib_s[30 + h * 5 + 2] + dotp(iw_s + (30 + h * 5 + 2) * 32, yp);
                float k3 = ib_s[30 + h * 5 + 3] + dotp(iw_s + (30 + h * 5 + 3) * 32, yp);
                float k4 = ib_s[30 + h * 5 + 4] + dotp(iw_s + (30 + h * 5 + 4) * 32, yp);
                float v0 = ib_s[60 + h * 5 + 0] + dotp(iw_s + (60 + h * 5 + 0) * 32, yp);
                float v1 = ib_s[60 + h * 5 + 1] + dotp(iw_s + (60 + h * 5 + 1) * 32, yp);
                float v2 = ib_s[60 + h * 5 + 2] + dotp(iw_s + (60 + h * 5 + 2) * 32, yp);
                float v3 = ib_s[60 + h * 5 + 3] + dotp(iw_s + (60 + h * 5 + 3) * 32, yp);
                float v4 = ib_s[60 + h * 5 + 4] + dotp(iw_s + (60 + h * 5 + 4) * 32, yp);

                ulonglong2 kk; kk.x = pk2(k0, k1); kk.y = pk2(k2, k3);
                KA[j * 32 + r]  = kk;
                KV4[j * 32 + r] = pk2(k4, v4);
                ulonglong2 vv; vv.x = pk2(v0, v1); vv.y = pk2(v2, v3);
                VA[j * 32 + r]  = vv;
            }
        }
        __syncwarp();
        if (act) {
            // ---- MERGED attention: all 3 heads in ONE t-loop (3x ILP) -----
            u64 a01[3] = {0ull, 0ull, 0ull};
            u64 a23[3] = {0ull, 0ull, 0ull};
            float a4[3] = {0.f, 0.f, 0.f};
            float es[3] = {0.f, 0.f, 0.f};
#pragma unroll 4
            for (int t = 0; t < S; t++) {
#pragma unroll
                for (int j = 0; j < 3; j++) {
                    ulonglong2 ka = KA[j * 32 + t];
                    float2 kv4 = upk2(KV4[j * 32 + t]);
                    u64 s2 = f2fma(ka.x, q01[j], f2fma(ka.y, q23[j], 0ull));
                    float2 sp = upk2(s2);
                    float e = ex2f(fmaf(q4[j], kv4.x, sp.x + sp.y));
                    u64 ee = pk2(e, e);
                    ulonglong2 va = VA[j * 32 + t];
                    a01[j] = f2fma(ee, va.x, a01[j]);
                    a23[j] = f2fma(ee, va.y, a23[j]);
                    a4[j]  = fmaf(e, kv4.y, a4[j]);
                    es[j] += e;
                }
            }
#pragma unroll
            for (int j = 0; j < 3; j++) {
                const int h = g * 3 + j;
                float inv = rcpf(es[j]);
                float2 p01 = upk2(a01[j]), p23 = upk2(a23[j]);
                float* os = OS + r * 33 + h * 5;
                os[0] = p01.x * inv;
                os[1] = p01.y * inv;
                os[2] = p23.x * inv;
                os[3] = p23.y * inv;
                os[4] = a4[j] * inv;
            }
        }
        __syncwarp();   // protects K/V rewrite (g=0) and OS-before-mean (g=1)
    }

    // ---- column mean over rows (mean commutes with out-proj) --------------
    float m = 0.f;
    if (r < 30) {
#pragma unroll
        for (int t = 0; t < S; t++) m += OS[t * 33 + r];
        m *= invS;
    }

    // ---- emb = ob + ow @ mean via owT (conflict-free) + shuffle -----------
    float emb = (r < 30) ? ob_s[r] : 0.f;
#pragma unroll
    for (int c = 0; c < 30; c++) {
        float mc = __shfl_sync(0xffffffffu, m, c);
        float wc = owT_s[c * 32 + r];        // lane r -> bank r, no conflict
        emb = fmaf(mc, wc, emb);
    }
    return emb;
}

// ===========================================================================
// hop2: 8 sequences/CTA (one per warp), 65536 sequences, exact grid.
// ===========================================================================
#define WPC2 8
#define NSEQ2 (NB * 16)
#define SMEM1_FLOATS (4960 + WPC2 * BUFF)    // 21088 -> 84,352 B

__global__ void __launch_bounds__(256, 2) hop2_kernel(
    const float* __restrict__ x2,
    const float* __restrict__ lw, const float* __restrict__ lb,
    const float* __restrict__ iw, const float* __restrict__ ib,
    const float* __restrict__ ow, const float* __restrict__ ob) {
    extern __shared__ float sm[];
    const int tid = threadIdx.x;
    stage_weights(sm, tid, 256, lw, lb, iw, ib, ow, ob);
    __syncthreads();

    const int seq = tid >> 5, r = tid & 31;
    const long sg = (long)blockIdx.x * WPC2 + seq;
    float* buf = sm + 4960 + seq * BUFF;
    const float* xrow = x2 + (sg * 32 + r) * 30;

    float emb = run_layer<32, true>(r, xrow, sm, buf, 1.f / 32.f);
    if (r < 30) g_h1[sg * 30 + r] = emb;
}

// ===========================================================================
// hop1: 6 nodes/CTA (192 thr) + classifier MLP + 2-class softmax (guarded).
// ===========================================================================
#define WPC1 6
#define OFF_CW1P (4960 + WPC1 * BUFF)    // 17056
#define OFF_CB1  (OFF_CW1P + 64 * 31)    // 19040
#define OFF_CW2P (OFF_CB1 + 64)          // 19104
#define OFF_CB2  (OFF_CW2P + 64 * 65)    // 23264
#define OFF_CW3  (OFF_CB2 + 64)          // 23328
#define OFF_CB3  (OFF_CW3 + 128)         // 23456
#define OFF_EMB  (OFF_CB3 + 4)           // 23460
#define OFF_HA   (OFF_EMB + WPC1 * 32)   // 23652
#define OFF_HB   (OFF_HA + WPC1 * 64)    // 24036
#define SMEM2_FLOATS (OFF_HB + WPC1 * 64)  // 24420 -> 97,680 B

__global__ void __launch_bounds__(192, 2) hop1_kernel(
    const float* __restrict__ self_feat,
    const float* __restrict__ lw, const float* __restrict__ lb,
    const float* __restrict__ iw, const float* __restrict__ ib,
    const float* __restrict__ ow, const float* __restrict__ ob,
    const float* __restrict__ cw1, const float* __restrict__ cb1,
    const float* __restrict__ cw2, const float* __restrict__ cb2,
    const float* __restrict__ cw3, const float* __restrict__ cb3,
    float* __restrict__ out) {
    extern __shared__ float sm[];
    const int tid = threadIdx.x;
    stage_weights(sm, tid, 192, lw, lb, iw, ib, ow, ob);
    float* cw1p = sm + OFF_CW1P;
    float* cb1s = sm + OFF_CB1;
    float* cw2p = sm + OFF_CW2P;
    float* cb2s = sm + OFF_CB2;
    float* cw3s = sm + OFF_CW3;
    float* cb3s = sm + OFF_CB3;
    float* embS = sm + OFF_EMB;
    float* hA   = sm + OFF_HA;
    float* hB   = sm + OFF_HB;
    for (int i = tid; i < 64 * 31; i += 192) {
        int row = i / 31, c = i % 31;
        cw1p[i] = (c < 30) ? cw1[row * 30 + c] : 0.f;
    }
    for (int i = tid; i < 64 * 65; i += 192) {
        int row = i / 65, c = i % 65;
        cw2p[i] = (c < 64) ? cw2[row * 64 + c] : 0.f;
    }
    if (tid < 64)  { cb1s[tid] = cb1[tid]; cb2s[tid] = cb2[tid]; }
    if (tid < 128) cw3s[tid] = cw3[tid];
    if (tid < 2)   cb3s[tid] = cb3[tid];
    __syncthreads();

    const int seq = tid >> 5, r = tid & 31;
    const int b = blockIdx.x * WPC1 + seq;
    if (b >= NB) return;
    float* buf = sm + 4960 + seq * BUFF;
    const float* xrow = (r < 16) ? (g_h1 + ((long)b * 16 + r) * 30)
                                 : (self_feat + (long)b * 30);

    float m = run_layer<17, false>(r, xrow, sm, buf, 1.f / 17.f);
    if (r < 30) embS[seq * 32 + r] = m;
    __syncwarp();

    // ---- classifier MLP (per warp) ----------------------------------------
    const float* emb = embS + seq * 32;
#pragma unroll
    for (int half = 0; half < 2; half++) {
        int j = r + 32 * half;
        float acc = cb1s[j];
#pragma unroll
        for (int k = 0; k < 30; k++) acc += emb[k] * cw1p[j * 31 + k];
        hA[seq * 64 + j] = fmaxf(acc, NEG * acc);
    }
    __syncwarp();
#pragma unroll
    for (int half = 0; half < 2; half++) {
        int j = r + 32 * half;
        float acc = cb2s[j];
#pragma unroll
        for (int k = 0; k < 64; k++) acc += hA[seq * 64 + k] * cw2p[j * 65 + k];
        hB[seq * 64 + j] = fmaxf(acc, NEG * acc);
    }
    __syncwarp();
    if (r < 2) {
        float acc = cb3s[r];
#pragma unroll
        for (int k = 0; k < 64; k++) acc += hB[seq * 64 + k] * cw3s[r * 64 + k];
        embS[seq * 32 + 30 + r] = acc;
    }
    __syncwarp();
    if (r == 0) {
        float l0 = embS[seq * 32 + 30], l1 = embS[seq * 32 + 31];
        float mx = fmaxf(l0, l1);
        float e0 = __expf(l0 - mx), e1 = __expf(l1 - mx);
        float inv = 1.f / (e0 + e1);
        out[(long)b * 2 + 0] = e0 * inv;
        out[(long)b * 2 + 1] = e1 * inv;
    }
}

// ===========================================================================
extern "C" void kernel_launch(void* const* d_in, const int* in_sizes, int n_in,
                              void* d_out, int out_size) {
    const float* x2   = (const float*)d_in[0];
    const float* self = (const float*)d_in[1];
    const float* lw2  = (const float*)d_in[2];
    const float* lb2  = (const float*)d_in[3];
    const float* iw2  = (const float*)d_in[4];
    const float* ib2  = (const float*)d_in[5];
    const float* ow2  = (const float*)d_in[6];
    const float* ob2  = (const float*)d_in[7];
    const float* lw1  = (const float*)d_in[8];
    const float* lb1  = (const float*)d_in[9];
    const float* iw1  = (const float*)d_in[10];
    const float* ib1  = (const float*)d_in[11];
    const float* ow1  = (const float*)d_in[12];
    const float* ob1  = (const float*)d_in[13];
    const float* cw1  = (const float*)d_in[14];
    const float* cb1  = (const float*)d_in[15];
    const float* cw2  = (const float*)d_in[16];
    const float* cb2  = (const float*)d_in[17];
    const float* cw3  = (const float*)d_in[18];
    const float* cb3  = (const float*)d_in[19];
    float* out = (float*)d_out;

    const int smem1 = SMEM1_FLOATS * 4;
    const int smem2 = SMEM2_FLOATS * 4;
    cudaFuncSetAttribute(hop2_kernel,
                         cudaFuncAttributeMaxDynamicSharedMemorySize, smem1);
    cudaFuncSetAttribute(hop1_kernel,
                         cudaFuncAttributeMaxDynamicSharedMemorySize, smem2);

    hop2_kernel<<<NSEQ2 / WPC2, 256, smem1>>>(x2, lw2, lb2, iw2, ib2, ow2, ob2);
    hop1_kernel<<<(NB + WPC1 - 1) / WPC1, 192, smem2>>>(
        self, lw1, lb1, iw1, ib1, ow1, ob1,
        cw1, cb1, cw2, cb2, cw3, cb3, out);
}